// round 16
// baseline (speedup 1.0000x reference)
#include <cuda_runtime.h>
#include <cuda_bf16.h>

#define IN_F   4096
#define OUT_F  4098
#define BATCH  2048
#define QUADS  1025          // ceil(OUT_F/4); last quad has 2 valid columns
#define ROWS_PER_BLK 4
#define TAP_PAD 4100         // OUT_F rounded up to multiple of 4

// SoA folded coefficients: out[b,j] = tap0[j]*x[b,j] + tap1[j]*x[b,j-1] + tap2[j]*x[b,j-2]
// Invalid taps (and pad beyond OUT_F) are exactly 0.
__device__ float g_tap0[TAP_PAD];
__device__ float g_tap1[TAP_PAD];
__device__ float g_tap2[TAP_PAD];

__global__ __launch_bounds__(256)
void coeff_kernel(const float* __restrict__ weight, const float* __restrict__ bias) {
    int j = blockIdx.x * blockDim.x + threadIdx.x;
    if (j >= TAP_PAD) return;
    if (j >= OUT_F) { g_tap0[j] = 0.f; g_tap1[j] = 0.f; g_tap2[j] = 0.f; return; }
    float m = 1.0f + bias[j];
    int n_hi = min(j, IN_F - 1);          // last scan step touching column j
    float c[3];
#pragma unroll
    for (int k = 0; k < 3; ++k) {
        int n = j - k;                    // scan step contributing via tap k
        float v = 0.0f;
        if (n >= 0 && n < IN_F) {
            int p = n_hi - n + 1;         // multiplies applied after this add (1..3)
            float mp = m;
            if (p >= 2) mp *= m;
            if (p >= 3) mp *= m;
            v = weight[(size_t)j * IN_F + n] * mp;
        }
        c[k] = v;
    }
    g_tap0[j] = c[0]; g_tap1[j] = c[1]; g_tap2[j] = c[2];
}

// Thread owns columns [4q, 4q+4) for 4 rows (fully unrolled, loads batched).
// Coefficients are SoA -> 3 coalesced LDG.128 per thread, reused for 4 rows.
__global__ __launch_bounds__(256)
void spread_kernel(const float* __restrict__ x, float* __restrict__ out) {
    int q = blockIdx.x * blockDim.x + threadIdx.x;
    if (q >= QUADS) return;
    int j  = q * 4;
    int jc = min(j, IN_F - 4);             // clamp v load for j==4096 (its coeffs are 0)
    int ja = max(j - 2, 0);                // clamp a load for j==0   (its coeffs are 0)

    // coalesced coefficient loads: consecutive threads -> consecutive 16B
    float4 t0 = *reinterpret_cast<const float4*>(&g_tap0[j]);
    float4 t1 = *reinterpret_cast<const float4*>(&g_tap1[j]);
    float4 t2 = *reinterpret_cast<const float4*>(&g_tap2[j]);

    int b0 = blockIdx.y * ROWS_PER_BLK;    // multiple of 4 -> r parity == row parity
    const float* xr  = x   + (size_t)b0 * IN_F;
    float*       orw = out + (size_t)b0 * OUT_F;

    // batch all x loads first (MLP=8)
    float4 v[ROWS_PER_BLK];
    float2 a[ROWS_PER_BLK];
#pragma unroll
    for (int r = 0; r < ROWS_PER_BLK; ++r) {
        const float* p = xr + (size_t)r * IN_F;
        v[r] = *reinterpret_cast<const float4*>(p + jc);  // x[j..j+3]
        a[r] = *reinterpret_cast<const float2*>(p + ja);  // x[j-2],x[j-1]
    }

    bool full = (j < IN_F);                // j<=4092: 4 valid cols; j==4096: 2 cols
#pragma unroll
    for (int r = 0; r < ROWS_PER_BLK; ++r) {
        float o0 = t0.x * v[r].x + t1.x * a[r].y + t2.x * a[r].x;
        float o1 = t0.y * v[r].y + t1.y * v[r].x + t2.y * a[r].y;
        float o2 = t0.z * v[r].z + t1.z * v[r].y + t2.z * v[r].x;
        float o3 = t0.w * v[r].w + t1.w * v[r].z + t2.w * v[r].y;
        float* po = orw + (size_t)r * OUT_F + j;
        if (full) {
            if ((r & 1) == 0) {
                // even row: (b*OUT_F + j) % 4 == 0 -> 16B-aligned STG.128
                *reinterpret_cast<float4*>(po) = make_float4(o0, o1, o2, o3);
            } else {
                *reinterpret_cast<float2*>(po)     = make_float2(o0, o1);
                *reinterpret_cast<float2*>(po + 2) = make_float2(o2, o3);
            }
        } else {
            // last quad: columns 4096, 4097 only (t0.x = t0.y = t1.y = 0 there,
            // so the clamped v values cancel; o0/o1 reduce to the valid taps)
            *reinterpret_cast<float2*>(po) = make_float2(o0, o1);
        }
    }
}

extern "C" void kernel_launch(void* const* d_in, const int* in_sizes, int n_in,
                              void* d_out, int out_size) {
    const float* x      = (const float*)d_in[0];
    const float* weight = (const float*)d_in[1];
    const float* bias   = (const float*)d_in[2];
    float* out = (float*)d_out;

    coeff_kernel<<<(TAP_PAD + 255) / 256, 256>>>(weight, bias);

    dim3 grid((QUADS + 255) / 256, BATCH / ROWS_PER_BLK);
    spread_kernel<<<grid, 256>>>(x, out);
}